// round 12
// baseline (speedup 1.0000x reference)
#include <cuda_runtime.h>
#include <cuda_fp16.h>
#include <cstdint>

// ---------------------------------------------------------------------------
// Signed 3-layer GCN + mean-pool + LayerNorm.
//   per layer: z_pos/z_neg = (A_sign + selfdiag) @ h   (one edge pass, CSR by dst)
//              h' = relu(z_pos@Wp + bp) - relu(z_neg@Wn + bn)
// h AND z live in fp16. GEMM: fp16 m16n8k16 mma, W split fp16 hi+lo (~fp32
// weight precision), fp32 accumulate. edge_index / batch are int32.
// R12: agg inner loop is fixed-trip (32) + predicated + unrolled -> high MLP.
// ---------------------------------------------------------------------------

#define DD    128
#define MAXN  100352            // 784 * 128, padded node capacity
#define MAXE  3200000
#define MAXG  64
#define EPSLN 1e-5f

__device__ __half g_zpos[(size_t)MAXN * DD];
__device__ __half g_zneg[(size_t)MAXN * DD];
__device__ __half g_h16A[(size_t)MAXN * DD];
__device__ __half g_h16B[(size_t)MAXN * DD];
__device__ int    g_esrc [MAXE];
__device__ float  g_ecoef[MAXE];
__device__ int    g_rowptr[MAXN + 1];
__device__ int    g_cntp[MAXN];
__device__ int    g_cntn[MAXN];
__device__ int    g_cursor[MAXN];
__device__ int    g_cntall[MAXN];
__device__ float  g_dinvp[MAXN];
__device__ float  g_dinvn[MAXN];
__device__ float  g_selfp[MAXN];
__device__ float  g_selfn[MAXN];
__device__ int    g_bsum[256];
__device__ int    g_boff[256];
__device__ float  g_pool[MAXG * DD];
__device__ int    g_pcnt[MAXG];

__device__ __forceinline__ __half* hbuf16(int s) { return s == 0 ? g_h16A : g_h16B; }
__device__ __forceinline__ int clampi(int v, int hi) {
    return v < 0 ? 0 : (v >= hi ? hi - 1 : v);
}

#define MMA_F16(d0,d1,d2,d3,a0,a1,a2,a3,b0,b1)                               \
    asm volatile("mma.sync.aligned.m16n8k16.row.col.f32.f16.f16.f32 "        \
                 "{%0,%1,%2,%3}, {%4,%5,%6,%7}, {%8,%9}, {%0,%1,%2,%3};"     \
                 : "+f"(d0), "+f"(d1), "+f"(d2), "+f"(d3)                    \
                 : "r"(a0), "r"(a1), "r"(a2), "r"(a3), "r"(b0), "r"(b1))

// ---------------------------------------------------------------- init
__global__ void k_init(int N) {
    int i = blockIdx.x * blockDim.x + threadIdx.x;
    if (i < N) { g_cntp[i] = 0; g_cntn[i] = 0; g_cursor[i] = 0; }
    if (i < MAXG * DD) g_pool[i] = 0.f;
    if (i < MAXG) g_pcnt[i] = 0;
}

// ---------------------------------------------------------------- x -> fp16
__global__ void k_x2h(const float* __restrict__ x, int total) {
    int i = blockIdx.x * blockDim.x + threadIdx.x;
    if (i < total) {
        float2 v = *(const float2*)(x + (size_t)i * 2);
        *(__half2*)(g_h16A + (size_t)i * 2) = __floats2half2_rn(v.x, v.y);
    }
}

// ---------------------------------------------------------------- degree count
__global__ void k_degree(const int* __restrict__ ei,
                         const float* __restrict__ ew, int E, int N) {
    int e = blockIdx.x * blockDim.x + threadIdx.x;
    if (e >= E) return;
    int dst = clampi(ei[E + e], N);
    float w = ew[e];
    if (w > 0.f)      atomicAdd(&g_cntp[dst], 1);
    else if (w < 0.f) atomicAdd(&g_cntn[dst], 1);
}

// ---------------------------------------------------------------- node params
__global__ void k_nodeparams(int N) {
    int v = blockIdx.x * blockDim.x + threadIdx.x;
    if (v >= N) return;
    int cp = g_cntp[v], cn = g_cntn[v];
    float dp = 1.f + (float)cp;
    float dn = 1.f + (float)cn;
    g_dinvp[v] = rsqrtf(dp);
    g_dinvn[v] = rsqrtf(dn);
    g_selfp[v] = 1.f / dp;
    g_selfn[v] = 1.f / dn;
    g_cntall[v] = cp + cn;
}

// ---------------------------------------------------------------- scan stage 1
__global__ void k_scan1(int N) {
    __shared__ int sm[32];
    int i = blockIdx.x * 1024 + threadIdx.x;
    int v = (i < N) ? g_cntall[i] : 0;
    int lane = threadIdx.x & 31, w = threadIdx.x >> 5;
    #pragma unroll
    for (int o = 16; o > 0; o >>= 1) v += __shfl_down_sync(0xffffffffu, v, o);
    if (lane == 0) sm[w] = v;
    __syncthreads();
    if (w == 0) {
        int t = sm[lane];
        #pragma unroll
        for (int o = 16; o > 0; o >>= 1) t += __shfl_down_sync(0xffffffffu, t, o);
        if (lane == 0) g_bsum[blockIdx.x] = t;
    }
}

// ---------------------------------------------------------------- scan stage 2
__global__ void k_scan2(int nb, int N) {
    if (threadIdx.x == 0 && blockIdx.x == 0) {
        int run = 0;
        for (int b = 0; b < nb; b++) { g_boff[b] = run; run += g_bsum[b]; }
        g_rowptr[N] = run;
    }
}

// ---------------------------------------------------------------- scan stage 3
__global__ void k_scan3(int N) {
    __shared__ int ws[32];
    int i = blockIdx.x * 1024 + threadIdx.x;
    int v = (i < N) ? g_cntall[i] : 0;
    int lane = threadIdx.x & 31, w = threadIdx.x >> 5;
    int x = v;
    #pragma unroll
    for (int o = 1; o < 32; o <<= 1) {
        int y = __shfl_up_sync(0xffffffffu, x, o);
        if (lane >= o) x += y;
    }
    if (lane == 31) ws[w] = x;
    __syncthreads();
    if (threadIdx.x < 32) {
        int t = ws[threadIdx.x];
        int y = t;
        #pragma unroll
        for (int o = 1; o < 32; o <<= 1) {
            int z = __shfl_up_sync(0xffffffffu, y, o);
            if (threadIdx.x >= o) y += z;
        }
        ws[threadIdx.x] = y - t;   // exclusive warp offset
    }
    __syncthreads();
    if (i < N) g_rowptr[i] = (x - v) + ws[w] + g_boff[blockIdx.x];
}

// ---------------------------------------------------------------- CSR scatter
__global__ void k_scatter(const int* __restrict__ ei,
                          const float* __restrict__ ew, int E, int N) {
    int e = blockIdx.x * blockDim.x + threadIdx.x;
    if (e >= E) return;
    float w = ew[e];
    if (w == 0.f) return;
    int s = clampi(ei[e], N);
    int d = clampi(ei[E + e], N);
    int pos = g_rowptr[d] + atomicAdd(&g_cursor[d], 1);
    float c;
    if (w > 0.f) c =  g_dinvp[s] * g_dinvp[d];
    else         c = -(g_dinvn[s] * g_dinvn[d]);
    g_esrc[pos]  = s;
    g_ecoef[pos] = c;
}

// ---------------------------------------------------------------- aggregation
// one warp per destination node; lane = 4 consecutive columns (4 halfs = 8B).
// Fixed-trip predicated inner loop (32 iters, unrolled) -> deep load MLP.
// Invalid lanes carry c=0 (contributes 0) and s=0 (h[0] broadcast, L2 hot).
__global__ void __launch_bounds__(256) k_agg(int insel, int N) {
    const __half* h = hbuf16(insel);
    int gw   = (blockIdx.x * blockDim.x + threadIdx.x) >> 5;
    int lane = threadIdx.x & 31;
    if (gw >= N) return;
    int v = gw;
    int beg = g_rowptr[v], end = g_rowptr[v + 1];

    float4 aP = make_float4(0.f, 0.f, 0.f, 0.f);
    float4 aN = make_float4(0.f, 0.f, 0.f, 0.f);

    for (int base = beg; base < end; base += 32) {
        int idx = base + lane;
        int s = 0; float c = 0.f;
        if (idx < end) { s = g_esrc[idx]; c = g_ecoef[idx]; }
        #pragma unroll
        for (int j = 0; j < 32; j++) {
            int   sj = __shfl_sync(0xffffffffu, s, j);
            float cj = __shfl_sync(0xffffffffu, c, j);
            uint2 raw = __ldg(((const uint2*)(h + (size_t)sj * DD)) + lane);
            float2 f01 = __half22float2(*(__half2*)&raw.x);
            float2 f23 = __half22float2(*(__half2*)&raw.y);
            if (cj > 0.f) {
                aP.x += cj * f01.x; aP.y += cj * f01.y;
                aP.z += cj * f23.x; aP.w += cj * f23.y;
            } else {
                float m = -cj;                 // cj==0 -> adds 0
                aN.x += m * f01.x; aN.y += m * f01.y;
                aN.z += m * f23.x; aN.w += m * f23.y;
            }
        }
    }
    // self-loop terms
    uint2 raw = __ldg(((const uint2*)(h + (size_t)v * DD)) + lane);
    float2 f01 = __half22float2(*(__half2*)&raw.x);
    float2 f23 = __half22float2(*(__half2*)&raw.y);
    float sp = g_selfp[v], sn = g_selfn[v];
    aP.x += sp * f01.x; aP.y += sp * f01.y; aP.z += sp * f23.x; aP.w += sp * f23.y;
    aN.x += sn * f01.x; aN.y += sn * f01.y; aN.z += sn * f23.x; aN.w += sn * f23.y;

    uint2 zp, zn;
    *(__half2*)&zp.x = __floats2half2_rn(aP.x, aP.y);
    *(__half2*)&zp.y = __floats2half2_rn(aP.z, aP.w);
    *(__half2*)&zn.x = __floats2half2_rn(aN.x, aN.y);
    *(__half2*)&zn.y = __floats2half2_rn(aN.z, aN.w);
    ((uint2*)(g_zpos + (size_t)v * DD))[lane] = zp;
    ((uint2*)(g_zneg + (size_t)v * DD))[lane] = zn;
}

// ---------------------------------------------------------------- fp16 GEMM
// sub=0: out16 = fp16(relu(A@W + b));  sub=1: out16 = fp16(out16 - relu(A@W + b))
// A: [Mpad,128] fp16. W: fp32 -> fp16 hi+lo (hi+lo carries ~22 mantissa bits).
// m16n8k16 mma, fp32 acc. 256 thr = 8 warps; warp tile 32(m) x 64(n).
#define KC2   32
#define ASTR  40
__global__ void __launch_bounds__(256) k_gemm_f16(int asel,
                                                  const float* __restrict__ W,
                                                  const float* __restrict__ bias,
                                                  int outsel, int sub) {
    const __half* A = (asel == 0) ? g_zpos : g_zneg;
    __half* out = hbuf16(outsel);

    __shared__ __half As [128 * ASTR];
    __shared__ __half Bhi[128 * ASTR];
    __shared__ __half Blo[128 * ASTR];
    __shared__ float  bs [128];

    const int tid  = threadIdx.x;
    const int lane = tid & 31;
    const int wid  = tid >> 5;
    const int gr   = lane >> 2;
    const int ct   = lane & 3;
    const int wm   = (wid & 3) * 32;
    const int wn   = (wid >> 2) * 64;
    const int blockM = blockIdx.x * 128;

    if (tid < 128) bs[tid] = bias[tid];

    float acc[2][8][4];
    #pragma unroll
    for (int im = 0; im < 2; im++)
        #pragma unroll
        for (int in = 0; in < 8; in++)
            #pragma unroll
            for (int q = 0; q < 4; q++) acc[im][in][q] = 0.f;

    for (int k0 = 0; k0 < 128; k0 += KC2) {
        {
            int f = tid;
            #pragma unroll
            for (int it = 0; it < 2; it++, f += 256) {
                int row = f >> 2, kq = (f & 3) * 8;
                *(uint4*)&As[row * ASTR + kq] =
                    *(const uint4*)(A + (size_t)(blockM + row) * 128 + k0 + kq);
            }
        }
        {
            int kl = tid >> 3;
            int n0 = (tid & 7) * 16;
            const float* wr = W + (size_t)(k0 + kl) * 128 + n0;
            #pragma unroll
            for (int j = 0; j < 16; j++) {
                float w = wr[j];
                __half hi = __float2half_rn(w);
                float lo = w - __half2float(hi);
                int n = n0 + j;
                Bhi[n * ASTR + kl] = hi;
                Blo[n * ASTR + kl] = __float2half_rn(lo);
            }
        }
        __syncthreads();

        #pragma unroll
        for (int ks = 0; ks < KC2; ks += 16) {
            uint32_t a[2][4];
            #pragma unroll
            for (int im = 0; im < 2; im++) {
                int r = wm + im * 16;
                a[im][0] = *(uint32_t*)&As[(r + gr)     * ASTR + ks + 2 * ct];
                a[im][1] = *(uint32_t*)&As[(r + 8 + gr) * ASTR + ks + 2 * ct];
                a[im][2] = *(uint32_t*)&As[(r + gr)     * ASTR + ks + 2 * ct + 8];
                a[im][3] = *(uint32_t*)&As[(r + 8 + gr) * ASTR + ks + 2 * ct + 8];
            }
            #pragma unroll
            for (int in = 0; in < 8; in++) {
                int n = wn + in * 8 + gr;
                uint32_t bh0 = *(uint32_t*)&Bhi[n * ASTR + ks + 2 * ct];
                uint32_t bh1 = *(uint32_t*)&Bhi[n * ASTR + ks + 2 * ct + 8];
                uint32_t bl0 = *(uint32_t*)&Blo[n * ASTR + ks + 2 * ct];
                uint32_t bl1 = *(uint32_t*)&Blo[n * ASTR + ks + 2 * ct + 8];
                #pragma unroll
                for (int im = 0; im < 2; im++) {
                    MMA_F16(acc[im][in][0], acc[im][in][1],
                            acc[im][in][2], acc[im][in][3],
                            a[im][0], a[im][1], a[im][2], a[im][3], bh0, bh1);
                    MMA_F16(acc[im][in][0], acc[im][in][1],
                            acc[im][in][2], acc[im][in][3],
                            a[im][0], a[im][1], a[im][2], a[im][3], bl0, bl1);
                }
            }
        }
        __syncthreads();
    }

    #pragma unroll
    for (int im = 0; im < 2; im++) {
        int r0 = blockM + wm + im * 16 + gr;
        #pragma unroll
        for (int in = 0; in < 8; in++) {
            int col = wn + in * 8 + ct * 2;
            float b0 = bs[col], b1 = bs[col + 1];
            __half2* p0 = (__half2*)(out + (size_t)r0 * 128 + col);
            __half2* p1 = (__half2*)(out + (size_t)(r0 + 8) * 128 + col);
            float r00 = fmaxf(acc[im][in][0] + b0, 0.f);
            float r01 = fmaxf(acc[im][in][1] + b1, 0.f);
            float r10 = fmaxf(acc[im][in][2] + b0, 0.f);
            float r11 = fmaxf(acc[im][in][3] + b1, 0.f);
            if (sub) {
                float2 o0 = __half22float2(*p0);
                float2 o1 = __half22float2(*p1);
                *p0 = __floats2half2_rn(o0.x - r00, o0.y - r01);
                *p1 = __floats2half2_rn(o1.x - r10, o1.y - r11);
            } else {
                *p0 = __floats2half2_rn(r00, r01);
                *p1 = __floats2half2_rn(r10, r11);
            }
        }
    }
}

// ---------------------------------------------------------------- mean pool
__global__ void k_pool(int insel, const int* __restrict__ batch, int N, int G) {
    const __half* h = hbuf16(insel);
    int t = threadIdx.x;
    int v0 = blockIdx.x * 128;
    int vend = min(v0 + 128, N);
    float acc = 0.f;
    int curg = -1, cnt = 0;
    for (int v = v0; v < vend; v++) {
        int g = clampi(batch[v], G);
        if (g != curg) {
            if (curg >= 0) {
                atomicAdd(&g_pool[curg * DD + t], acc);
                if (t == 0) atomicAdd(&g_pcnt[curg], cnt);
            }
            curg = g; acc = 0.f; cnt = 0;
        }
        acc += __half2float(h[(size_t)v * DD + t]);
        cnt++;
    }
    if (curg >= 0) {
        atomicAdd(&g_pool[curg * DD + t], acc);
        if (t == 0) atomicAdd(&g_pcnt[curg], cnt);
    }
}

// ---------------------------------------------------------------- layernorm
__global__ void k_ln(const float* __restrict__ gamma,
                     const float* __restrict__ beta,
                     float* __restrict__ out) {
    __shared__ float sm[4];
    int g = blockIdx.x, t = threadIdx.x;
    int lane = t & 31, w = t >> 5;
    float cnt = fmaxf((float)g_pcnt[g], 1.f);
    float v = g_pool[g * DD + t] / cnt;

    float s = v;
    #pragma unroll
    for (int o = 16; o > 0; o >>= 1) s += __shfl_xor_sync(0xffffffffu, s, o);
    if (lane == 0) sm[w] = s;
    __syncthreads();
    float mu = (sm[0] + sm[1] + sm[2] + sm[3]) * (1.f / 128.f);
    __syncthreads();

    float d = v - mu;
    float s2 = d * d;
    #pragma unroll
    for (int o = 16; o > 0; o >>= 1) s2 += __shfl_xor_sync(0xffffffffu, s2, o);
    if (lane == 0) sm[w] = s2;
    __syncthreads();
    float var = (sm[0] + sm[1] + sm[2] + sm[3]) * (1.f / 128.f);

    out[g * DD + t] = d * rsqrtf(var + EPSLN) * gamma[t] + beta[t];
}

// ---------------------------------------------------------------- launch
extern "C" void kernel_launch(void* const* d_in, const int* in_sizes, int n_in,
                              void* d_out, int out_size) {
    const float* x     = (const float*)d_in[0];
    const int*   ei    = (const int*)d_in[1];
    const float* ew    = (const float*)d_in[2];
    const int*   batch = (const int*)d_in[3];
    const float* Wp    = (const float*)d_in[4];
    const float* bp    = (const float*)d_in[5];
    const float* Wn    = (const float*)d_in[6];
    const float* bn    = (const float*)d_in[7];
    const float* gamma = (const float*)d_in[8];
    const float* beta  = (const float*)d_in[9];

    int N = in_sizes[0] / DD;
    int E = in_sizes[1] / 2;
    int L = in_sizes[4] / (DD * DD);
    int G = out_size / DD;

    int nbN  = (N + 255) / 256;
    int nbE  = (E + 255) / 256;
    int nbSc = (N + 1023) / 1024;
    int nbAg = (N * 32 + 255) / 256;          // one warp per node
    int nbGm = (N + 127) / 128;               // 128-row GEMM tiles
    int nbPl = (N + 127) / 128;
    int nbCv = (N * DD / 2 + 255) / 256;      // x->fp16 (2 elems/thread)

    // preprocessing (per call; deterministic structure)
    k_init<<<nbN, 256>>>(N);
    k_x2h<<<nbCv, 256>>>(x, N * DD / 2);
    k_degree<<<nbE, 256>>>(ei, ew, E, N);
    k_nodeparams<<<nbN, 256>>>(N);
    k_scan1<<<nbSc, 1024>>>(N);
    k_scan2<<<1, 32>>>(nbSc, N);
    k_scan3<<<nbSc, 1024>>>(N);
    k_scatter<<<nbE, 256>>>(ei, ew, E, N);

    // layers: h16A holds x (layer0 input); ping-pong A(0)/B(1)
    int insel = 0;
    for (int l = 0; l < L; l++) {
        k_agg<<<nbAg, 256>>>(insel, N);
        int outsel = insel ^ 1;
        k_gemm_f16<<<nbGm, 256>>>(0, Wp + (size_t)l * DD * DD, bp + (size_t)l * DD, outsel, 0);
        k_gemm_f16<<<nbGm, 256>>>(1, Wn + (size_t)l * DD * DD, bn + (size_t)l * DD, outsel, 1);
        insel = outsel;
    }

    // pool + layernorm
    k_pool<<<nbPl, 128>>>(insel, batch, N, G);
    k_ln<<<G, 128>>>(gamma, beta, (float*)d_out);
}

// round 14
// speedup vs baseline: 1.1424x; 1.1424x over previous
#include <cuda_runtime.h>
#include <cuda_fp16.h>
#include <cstdint>

// ---------------------------------------------------------------------------
// Signed 3-layer GCN + mean-pool + LayerNorm.
//   per layer: z_pos/z_neg = (A_sign + selfdiag) @ h   (one edge pass, CSR by dst)
//              h' = relu(z_pos@Wp + bp) - relu(z_neg@Wn + bn)
// h AND z live in fp16. GEMM: fp16 m16n8k16 mma, W split fp16 hi+lo (~fp32
// weight precision), fp32 accumulate. edge_index / batch are int32.
// R13: agg inner loop unrolled by 4 (round-to-4 padding, batched loads).
// ---------------------------------------------------------------------------

#define DD    128
#define MAXN  100352            // 784 * 128, padded node capacity
#define MAXE  3200000
#define MAXG  64
#define EPSLN 1e-5f

__device__ __half g_zpos[(size_t)MAXN * DD];
__device__ __half g_zneg[(size_t)MAXN * DD];
__device__ __half g_h16A[(size_t)MAXN * DD];
__device__ __half g_h16B[(size_t)MAXN * DD];
__device__ int    g_esrc [MAXE];
__device__ float  g_ecoef[MAXE];
__device__ int    g_rowptr[MAXN + 1];
__device__ int    g_cntp[MAXN];
__device__ int    g_cntn[MAXN];
__device__ int    g_cursor[MAXN];
__device__ int    g_cntall[MAXN];
__device__ float  g_dinvp[MAXN];
__device__ float  g_dinvn[MAXN];
__device__ float  g_selfp[MAXN];
__device__ float  g_selfn[MAXN];
__device__ int    g_bsum[256];
__device__ int    g_boff[256];
__device__ float  g_pool[MAXG * DD];
__device__ int    g_pcnt[MAXG];

__device__ __forceinline__ __half* hbuf16(int s) { return s == 0 ? g_h16A : g_h16B; }
__device__ __forceinline__ int clampi(int v, int hi) {
    return v < 0 ? 0 : (v >= hi ? hi - 1 : v);
}

#define MMA_F16(d0,d1,d2,d3,a0,a1,a2,a3,b0,b1)                               \
    asm volatile("mma.sync.aligned.m16n8k16.row.col.f32.f16.f16.f32 "        \
                 "{%0,%1,%2,%3}, {%4,%5,%6,%7}, {%8,%9}, {%0,%1,%2,%3};"     \
                 : "+f"(d0), "+f"(d1), "+f"(d2), "+f"(d3)                    \
                 : "r"(a0), "r"(a1), "r"(a2), "r"(a3), "r"(b0), "r"(b1))

// ---------------------------------------------------------------- init
__global__ void k_init(int N) {
    int i = blockIdx.x * blockDim.x + threadIdx.x;
    if (i < N) { g_cntp[i] = 0; g_cntn[i] = 0; g_cursor[i] = 0; }
    if (i < MAXG * DD) g_pool[i] = 0.f;
    if (i < MAXG) g_pcnt[i] = 0;
}

// ---------------------------------------------------------------- x -> fp16
__global__ void k_x2h(const float* __restrict__ x, int total) {
    int i = blockIdx.x * blockDim.x + threadIdx.x;
    if (i < total) {
        float2 v = *(const float2*)(x + (size_t)i * 2);
        *(__half2*)(g_h16A + (size_t)i * 2) = __floats2half2_rn(v.x, v.y);
    }
}

// ---------------------------------------------------------------- degree count
__global__ void k_degree(const int* __restrict__ ei,
                         const float* __restrict__ ew, int E, int N) {
    int e = blockIdx.x * blockDim.x + threadIdx.x;
    if (e >= E) return;
    int dst = clampi(ei[E + e], N);
    float w = ew[e];
    if (w > 0.f)      atomicAdd(&g_cntp[dst], 1);
    else if (w < 0.f) atomicAdd(&g_cntn[dst], 1);
}

// ---------------------------------------------------------------- node params
__global__ void k_nodeparams(int N) {
    int v = blockIdx.x * blockDim.x + threadIdx.x;
    if (v >= N) return;
    int cp = g_cntp[v], cn = g_cntn[v];
    float dp = 1.f + (float)cp;
    float dn = 1.f + (float)cn;
    g_dinvp[v] = rsqrtf(dp);
    g_dinvn[v] = rsqrtf(dn);
    g_selfp[v] = 1.f / dp;
    g_selfn[v] = 1.f / dn;
    g_cntall[v] = cp + cn;
}

// ---------------------------------------------------------------- scan stage 1
__global__ void k_scan1(int N) {
    __shared__ int sm[32];
    int i = blockIdx.x * 1024 + threadIdx.x;
    int v = (i < N) ? g_cntall[i] : 0;
    int lane = threadIdx.x & 31, w = threadIdx.x >> 5;
    #pragma unroll
    for (int o = 16; o > 0; o >>= 1) v += __shfl_down_sync(0xffffffffu, v, o);
    if (lane == 0) sm[w] = v;
    __syncthreads();
    if (w == 0) {
        int t = sm[lane];
        #pragma unroll
        for (int o = 16; o > 0; o >>= 1) t += __shfl_down_sync(0xffffffffu, t, o);
        if (lane == 0) g_bsum[blockIdx.x] = t;
    }
}

// ---------------------------------------------------------------- scan stage 2
__global__ void k_scan2(int nb, int N) {
    if (threadIdx.x == 0 && blockIdx.x == 0) {
        int run = 0;
        for (int b = 0; b < nb; b++) { g_boff[b] = run; run += g_bsum[b]; }
        g_rowptr[N] = run;
    }
}

// ---------------------------------------------------------------- scan stage 3
__global__ void k_scan3(int N) {
    __shared__ int ws[32];
    int i = blockIdx.x * 1024 + threadIdx.x;
    int v = (i < N) ? g_cntall[i] : 0;
    int lane = threadIdx.x & 31, w = threadIdx.x >> 5;
    int x = v;
    #pragma unroll
    for (int o = 1; o < 32; o <<= 1) {
        int y = __shfl_up_sync(0xffffffffu, x, o);
        if (lane >= o) x += y;
    }
    if (lane == 31) ws[w] = x;
    __syncthreads();
    if (threadIdx.x < 32) {
        int t = ws[threadIdx.x];
        int y = t;
        #pragma unroll
        for (int o = 1; o < 32; o <<= 1) {
            int z = __shfl_up_sync(0xffffffffu, y, o);
            if (threadIdx.x >= o) y += z;
        }
        ws[threadIdx.x] = y - t;   // exclusive warp offset
    }
    __syncthreads();
    if (i < N) g_rowptr[i] = (x - v) + ws[w] + g_boff[blockIdx.x];
}

// ---------------------------------------------------------------- CSR scatter
__global__ void k_scatter(const int* __restrict__ ei,
                          const float* __restrict__ ew, int E, int N) {
    int e = blockIdx.x * blockDim.x + threadIdx.x;
    if (e >= E) return;
    float w = ew[e];
    if (w == 0.f) return;
    int s = clampi(ei[e], N);
    int d = clampi(ei[E + e], N);
    int pos = g_rowptr[d] + atomicAdd(&g_cursor[d], 1);
    float c;
    if (w > 0.f) c =  g_dinvp[s] * g_dinvp[d];
    else         c = -(g_dinvn[s] * g_dinvn[d]);
    g_esrc[pos]  = s;
    g_ecoef[pos] = c;
}

// ---------------------------------------------------------------- aggregation
// one warp per destination node; lane = 4 consecutive columns (4 halfs = 8B).
// Inner loop unrolled by 4 with round-to-4 padding: 4 independent gathers in
// flight, ~5% padded work. Padded lanes carry c=0 -> contribute exactly 0.
__global__ void __launch_bounds__(256) k_agg(int insel, int N) {
    const __half* h = hbuf16(insel);
    int gw   = (blockIdx.x * blockDim.x + threadIdx.x) >> 5;
    int lane = threadIdx.x & 31;
    if (gw >= N) return;
    int v = gw;
    int beg = g_rowptr[v], end = g_rowptr[v + 1];

    float4 aP = make_float4(0.f, 0.f, 0.f, 0.f);
    float4 aN = make_float4(0.f, 0.f, 0.f, 0.f);

    for (int base = beg; base < end; base += 32) {
        int idx = base + lane;
        int s = 0; float c = 0.f;
        if (idx < end) { s = g_esrc[idx]; c = g_ecoef[idx]; }
        int cnt4 = (min(32, end - base) + 3) & ~3;
        for (int j = 0; j < cnt4; j += 4) {
            int   sj[4]; float cj[4]; uint2 raw[4];
            #pragma unroll
            for (int u = 0; u < 4; u++) {
                sj[u] = __shfl_sync(0xffffffffu, s, j + u);
                cj[u] = __shfl_sync(0xffffffffu, c, j + u);
            }
            #pragma unroll
            for (int u = 0; u < 4; u++)
                raw[u] = __ldg(((const uint2*)(h + (size_t)sj[u] * DD)) + lane);
            #pragma unroll
            for (int u = 0; u < 4; u++) {
                float2 f01 = __half22float2(*(__half2*)&raw[u].x);
                float2 f23 = __half22float2(*(__half2*)&raw[u].y);
                float cu = cj[u];
                if (cu > 0.f) {
                    aP.x += cu * f01.x; aP.y += cu * f01.y;
                    aP.z += cu * f23.x; aP.w += cu * f23.y;
                } else {
                    float m = -cu;               // cu==0 -> adds 0
                    aN.x += m * f01.x; aN.y += m * f01.y;
                    aN.z += m * f23.x; aN.w += m * f23.y;
                }
            }
        }
    }
    // self-loop terms
    uint2 raw = __ldg(((const uint2*)(h + (size_t)v * DD)) + lane);
    float2 f01 = __half22float2(*(__half2*)&raw.x);
    float2 f23 = __half22float2(*(__half2*)&raw.y);
    float sp = g_selfp[v], sn = g_selfn[v];
    aP.x += sp * f01.x; aP.y += sp * f01.y; aP.z += sp * f23.x; aP.w += sp * f23.y;
    aN.x += sn * f01.x; aN.y += sn * f01.y; aN.z += sn * f23.x; aN.w += sn * f23.y;

    uint2 zp, zn;
    *(__half2*)&zp.x = __floats2half2_rn(aP.x, aP.y);
    *(__half2*)&zp.y = __floats2half2_rn(aP.z, aP.w);
    *(__half2*)&zn.x = __floats2half2_rn(aN.x, aN.y);
    *(__half2*)&zn.y = __floats2half2_rn(aN.z, aN.w);
    ((uint2*)(g_zpos + (size_t)v * DD))[lane] = zp;
    ((uint2*)(g_zneg + (size_t)v * DD))[lane] = zn;
}

// ---------------------------------------------------------------- fp16 GEMM
// sub=0: out16 = fp16(relu(A@W + b));  sub=1: out16 = fp16(out16 - relu(A@W + b))
// A: [Mpad,128] fp16. W: fp32 -> fp16 hi+lo (hi+lo carries ~22 mantissa bits).
// m16n8k16 mma, fp32 acc. 256 thr = 8 warps; warp tile 32(m) x 64(n).
#define KC2   32
#define ASTR  40
__global__ void __launch_bounds__(256) k_gemm_f16(int asel,
                                                  const float* __restrict__ W,
                                                  const float* __restrict__ bias,
                                                  int outsel, int sub) {
    const __half* A = (asel == 0) ? g_zpos : g_zneg;
    __half* out = hbuf16(outsel);

    __shared__ __half As [128 * ASTR];
    __shared__ __half Bhi[128 * ASTR];
    __shared__ __half Blo[128 * ASTR];
    __shared__ float  bs [128];

    const int tid  = threadIdx.x;
    const int lane = tid & 31;
    const int wid  = tid >> 5;
    const int gr   = lane >> 2;
    const int ct   = lane & 3;
    const int wm   = (wid & 3) * 32;
    const int wn   = (wid >> 2) * 64;
    const int blockM = blockIdx.x * 128;

    if (tid < 128) bs[tid] = bias[tid];

    float acc[2][8][4];
    #pragma unroll
    for (int im = 0; im < 2; im++)
        #pragma unroll
        for (int in = 0; in < 8; in++)
            #pragma unroll
            for (int q = 0; q < 4; q++) acc[im][in][q] = 0.f;

    for (int k0 = 0; k0 < 128; k0 += KC2) {
        {
            int f = tid;
            #pragma unroll
            for (int it = 0; it < 2; it++, f += 256) {
                int row = f >> 2, kq = (f & 3) * 8;
                *(uint4*)&As[row * ASTR + kq] =
                    *(const uint4*)(A + (size_t)(blockM + row) * 128 + k0 + kq);
            }
        }
        {
            int kl = tid >> 3;
            int n0 = (tid & 7) * 16;
            const float* wr = W + (size_t)(k0 + kl) * 128 + n0;
            #pragma unroll
            for (int j = 0; j < 16; j++) {
                float w = wr[j];
                __half hi = __float2half_rn(w);
                float lo = w - __half2float(hi);
                int n = n0 + j;
                Bhi[n * ASTR + kl] = hi;
                Blo[n * ASTR + kl] = __float2half_rn(lo);
            }
        }
        __syncthreads();

        #pragma unroll
        for (int ks = 0; ks < KC2; ks += 16) {
            uint32_t a[2][4];
            #pragma unroll
            for (int im = 0; im < 2; im++) {
                int r = wm + im * 16;
                a[im][0] = *(uint32_t*)&As[(r + gr)     * ASTR + ks + 2 * ct];
                a[im][1] = *(uint32_t*)&As[(r + 8 + gr) * ASTR + ks + 2 * ct];
                a[im][2] = *(uint32_t*)&As[(r + gr)     * ASTR + ks + 2 * ct + 8];
                a[im][3] = *(uint32_t*)&As[(r + 8 + gr) * ASTR + ks + 2 * ct + 8];
            }
            #pragma unroll
            for (int in = 0; in < 8; in++) {
                int n = wn + in * 8 + gr;
                uint32_t bh0 = *(uint32_t*)&Bhi[n * ASTR + ks + 2 * ct];
                uint32_t bh1 = *(uint32_t*)&Bhi[n * ASTR + ks + 2 * ct + 8];
                uint32_t bl0 = *(uint32_t*)&Blo[n * ASTR + ks + 2 * ct];
                uint32_t bl1 = *(uint32_t*)&Blo[n * ASTR + ks + 2 * ct + 8];
                #pragma unroll
                for (int im = 0; im < 2; im++) {
                    MMA_F16(acc[im][in][0], acc[im][in][1],
                            acc[im][in][2], acc[im][in][3],
                            a[im][0], a[im][1], a[im][2], a[im][3], bh0, bh1);
                    MMA_F16(acc[im][in][0], acc[im][in][1],
                            acc[im][in][2], acc[im][in][3],
                            a[im][0], a[im][1], a[im][2], a[im][3], bl0, bl1);
                }
            }
        }
        __syncthreads();
    }

    #pragma unroll
    for (int im = 0; im < 2; im++) {
        int r0 = blockM + wm + im * 16 + gr;
        #pragma unroll
        for (int in = 0; in < 8; in++) {
            int col = wn + in * 8 + ct * 2;
            float b0 = bs[col], b1 = bs[col + 1];
            __half2* p0 = (__half2*)(out + (size_t)r0 * 128 + col);
            __half2* p1 = (__half2*)(out + (size_t)(r0 + 8) * 128 + col);
            float r00 = fmaxf(acc[im][in][0] + b0, 0.f);
            float r01 = fmaxf(acc[im][in][1] + b1, 0.f);
            float r10 = fmaxf(acc[im][in][2] + b0, 0.f);
            float r11 = fmaxf(acc[im][in][3] + b1, 0.f);
            if (sub) {
                float2 o0 = __half22float2(*p0);
                float2 o1 = __half22float2(*p1);
                *p0 = __floats2half2_rn(o0.x - r00, o0.y - r01);
                *p1 = __floats2half2_rn(o1.x - r10, o1.y - r11);
            } else {
                *p0 = __floats2half2_rn(r00, r01);
                *p1 = __floats2half2_rn(r10, r11);
            }
        }
    }
}

// ---------------------------------------------------------------- mean pool
__global__ void k_pool(int insel, const int* __restrict__ batch, int N, int G) {
    const __half* h = hbuf16(insel);
    int t = threadIdx.x;
    int v0 = blockIdx.x * 128;
    int vend = min(v0 + 128, N);
    float acc = 0.f;
    int curg = -1, cnt = 0;
    for (int v = v0; v < vend; v++) {
        int g = clampi(batch[v], G);
        if (g != curg) {
            if (curg >= 0) {
                atomicAdd(&g_pool[curg * DD + t], acc);
                if (t == 0) atomicAdd(&g_pcnt[curg], cnt);
            }
            curg = g; acc = 0.f; cnt = 0;
        }
        acc += __half2float(h[(size_t)v * DD + t]);
        cnt++;
    }
    if (curg >= 0) {
        atomicAdd(&g_pool[curg * DD + t], acc);
        if (t == 0) atomicAdd(&g_pcnt[curg], cnt);
    }
}

// ---------------------------------------------------------------- layernorm
__global__ void k_ln(const float* __restrict__ gamma,
                     const float* __restrict__ beta,
                     float* __restrict__ out) {
    __shared__ float sm[4];
    int g = blockIdx.x, t = threadIdx.x;
    int lane = t & 31, w = t >> 5;
    float cnt = fmaxf((float)g_pcnt[g], 1.f);
    float v = g_pool[g * DD + t] / cnt;

    float s = v;
    #pragma unroll
    for (int o = 16; o > 0; o >>= 1) s += __shfl_xor_sync(0xffffffffu, s, o);
    if (lane == 0) sm[w] = s;
    __syncthreads();
    float mu = (sm[0] + sm[1] + sm[2] + sm[3]) * (1.f / 128.f);
    __syncthreads();

    float d = v - mu;
    float s2 = d * d;
    #pragma unroll
    for (int o = 16; o > 0; o >>= 1) s2 += __shfl_xor_sync(0xffffffffu, s2, o);
    if (lane == 0) sm[w] = s2;
    __syncthreads();
    float var = (sm[0] + sm[1] + sm[2] + sm[3]) * (1.f / 128.f);

    out[g * DD + t] = d * rsqrtf(var + EPSLN) * gamma[t] + beta[t];
}

// ---------------------------------------------------------------- launch
extern "C" void kernel_launch(void* const* d_in, const int* in_sizes, int n_in,
                              void* d_out, int out_size) {
    const float* x     = (const float*)d_in[0];
    const int*   ei    = (const int*)d_in[1];
    const float* ew    = (const float*)d_in[2];
    const int*   batch = (const int*)d_in[3];
    const float* Wp    = (const float*)d_in[4];
    const float* bp    = (const float*)d_in[5];
    const float* Wn    = (const float*)d_in[6];
    const float* bn    = (const float*)d_in[7];
    const float* gamma = (const float*)d_in[8];
    const float* beta  = (const float*)d_in[9];

    int N = in_sizes[0] / DD;
    int E = in_sizes[1] / 2;
    int L = in_sizes[4] / (DD * DD);
    int G = out_size / DD;

    int nbN  = (N + 255) / 256;
    int nbE  = (E + 255) / 256;
    int nbSc = (N + 1023) / 1024;
    int nbAg = (N * 32 + 255) / 256;          // one warp per node
    int nbGm = (N + 127) / 128;               // 128-row GEMM tiles
    int nbPl = (N + 127) / 128;
    int nbCv = (N * DD / 2 + 255) / 256;      // x->fp16 (2 elems/thread)

    // preprocessing (per call; deterministic structure)
    k_init<<<nbN, 256>>>(N);
    k_x2h<<<nbCv, 256>>>(x, N * DD / 2);
    k_degree<<<nbE, 256>>>(ei, ew, E, N);
    k_nodeparams<<<nbN, 256>>>(N);
    k_scan1<<<nbSc, 1024>>>(N);
    k_scan2<<<1, 32>>>(nbSc, N);
    k_scan3<<<nbSc, 1024>>>(N);
    k_scatter<<<nbE, 256>>>(ei, ew, E, N);

    // layers: h16A holds x (layer0 input); ping-pong A(0)/B(1)
    int insel = 0;
    for (int l = 0; l < L; l++) {
        k_agg<<<nbAg, 256>>>(insel, N);
        int outsel = insel ^ 1;
        k_gemm_f16<<<nbGm, 256>>>(0, Wp + (size_t)l * DD * DD, bp + (size_t)l * DD, outsel, 0);
        k_gemm_f16<<<nbGm, 256>>>(1, Wn + (size_t)l * DD * DD, bn + (size_t)l * DD, outsel, 1);
        insel = outsel;
    }

    // pool + layernorm
    k_pool<<<nbPl, 128>>>(insel, batch, N, G);
    k_ln<<<G, 128>>>(gamma, beta, (float*)d_out);
}

// round 15
// speedup vs baseline: 1.5323x; 1.3413x over previous
#include <cuda_runtime.h>
#include <cuda_fp16.h>
#include <cstdint>

// ---------------------------------------------------------------------------
// Signed 3-layer GCN + mean-pool + LayerNorm.
//   per layer: z_pos/z_neg = (A_sign + selfdiag) @ h   (one edge pass, CSR by dst)
//              h' = relu(z_pos@Wp + bp) - relu(z_neg@Wn + bn)
// h AND z live in fp16. GEMM: fp16 m16n8k16 mma, W pre-split fp16 hi+lo once
// per call (k_wprep, n-major), fp32 accumulate. edge_index / batch are int32.
// R15: W precompute + agg unroll-by-8.
// ---------------------------------------------------------------------------

#define DD    128
#define MAXN  100352            // 784 * 128, padded node capacity
#define MAXE  3200000
#define MAXG  64
#define MAXL  3
#define EPSLN 1e-5f

__device__ __half g_zpos[(size_t)MAXN * DD];
__device__ __half g_zneg[(size_t)MAXN * DD];
__device__ __half g_h16A[(size_t)MAXN * DD];
__device__ __half g_h16B[(size_t)MAXN * DD];
__device__ __half g_whi[(size_t)MAXL * 2 * DD * DD];   // [mat][n][k] n-major
__device__ __half g_wlo[(size_t)MAXL * 2 * DD * DD];
__device__ int    g_esrc [MAXE];
__device__ float  g_ecoef[MAXE];
__device__ int    g_rowptr[MAXN + 1];
__device__ int    g_cntp[MAXN];
__device__ int    g_cntn[MAXN];
__device__ int    g_cursor[MAXN];
__device__ int    g_cntall[MAXN];
__device__ float  g_dinvp[MAXN];
__device__ float  g_dinvn[MAXN];
__device__ float  g_selfp[MAXN];
__device__ float  g_selfn[MAXN];
__device__ int    g_bsum[256];
__device__ int    g_boff[256];
__device__ float  g_pool[MAXG * DD];
__device__ int    g_pcnt[MAXG];

__device__ __forceinline__ __half* hbuf16(int s) { return s == 0 ? g_h16A : g_h16B; }
__device__ __forceinline__ int clampi(int v, int hi) {
    return v < 0 ? 0 : (v >= hi ? hi - 1 : v);
}

#define MMA_F16(d0,d1,d2,d3,a0,a1,a2,a3,b0,b1)                               \
    asm volatile("mma.sync.aligned.m16n8k16.row.col.f32.f16.f16.f32 "        \
                 "{%0,%1,%2,%3}, {%4,%5,%6,%7}, {%8,%9}, {%0,%1,%2,%3};"     \
                 : "+f"(d0), "+f"(d1), "+f"(d2), "+f"(d3)                    \
                 : "r"(a0), "r"(a1), "r"(a2), "r"(a3), "r"(b0), "r"(b1))

// ---------------------------------------------------------------- init
__global__ void k_init(int N) {
    int i = blockIdx.x * blockDim.x + threadIdx.x;
    if (i < N) { g_cntp[i] = 0; g_cntn[i] = 0; g_cursor[i] = 0; }
    if (i < MAXG * DD) g_pool[i] = 0.f;
    if (i < MAXG) g_pcnt[i] = 0;
}

// ---------------------------------------------------------------- x -> fp16
__global__ void k_x2h(const float* __restrict__ x, int total) {
    int i = blockIdx.x * blockDim.x + threadIdx.x;
    if (i < total) {
        float2 v = *(const float2*)(x + (size_t)i * 2);
        *(__half2*)(g_h16A + (size_t)i * 2) = __floats2half2_rn(v.x, v.y);
    }
}

// ---------------------------------------------------------------- W -> fp16 hi/lo
// Wp/Wn are [L][k][n] row-major fp32. Output n-major: g_whi[mat][n*128+k],
// mat = l*2 (pos) / l*2+1 (neg).
__global__ void k_wprep(const float* __restrict__ Wp,
                        const float* __restrict__ Wn, int L) {
    int i = blockIdx.x * blockDim.x + threadIdx.x;
    int total = L * 2 * DD * DD;
    if (i >= total) return;
    int k   = i & 127;
    int n   = (i >> 7) & 127;
    int mat = i >> 14;           // 0..2L-1
    int l   = mat >> 1;
    const float* W = (mat & 1) ? Wn : Wp;
    float w = W[(size_t)l * DD * DD + k * DD + n];
    __half hi = __float2half_rn(w);
    float lo = w - __half2float(hi);
    g_whi[(size_t)mat * DD * DD + n * DD + k] = hi;
    g_wlo[(size_t)mat * DD * DD + n * DD + k] = __float2half_rn(lo);
}

// ---------------------------------------------------------------- degree count
__global__ void k_degree(const int* __restrict__ ei,
                         const float* __restrict__ ew, int E, int N) {
    int e = blockIdx.x * blockDim.x + threadIdx.x;
    if (e >= E) return;
    int dst = clampi(ei[E + e], N);
    float w = ew[e];
    if (w > 0.f)      atomicAdd(&g_cntp[dst], 1);
    else if (w < 0.f) atomicAdd(&g_cntn[dst], 1);
}

// ---------------------------------------------------------------- node params
__global__ void k_nodeparams(int N) {
    int v = blockIdx.x * blockDim.x + threadIdx.x;
    if (v >= N) return;
    int cp = g_cntp[v], cn = g_cntn[v];
    float dp = 1.f + (float)cp;
    float dn = 1.f + (float)cn;
    g_dinvp[v] = rsqrtf(dp);
    g_dinvn[v] = rsqrtf(dn);
    g_selfp[v] = 1.f / dp;
    g_selfn[v] = 1.f / dn;
    g_cntall[v] = cp + cn;
}

// ---------------------------------------------------------------- scan stage 1
__global__ void k_scan1(int N) {
    __shared__ int sm[32];
    int i = blockIdx.x * 1024 + threadIdx.x;
    int v = (i < N) ? g_cntall[i] : 0;
    int lane = threadIdx.x & 31, w = threadIdx.x >> 5;
    #pragma unroll
    for (int o = 16; o > 0; o >>= 1) v += __shfl_down_sync(0xffffffffu, v, o);
    if (lane == 0) sm[w] = v;
    __syncthreads();
    if (w == 0) {
        int t = sm[lane];
        #pragma unroll
        for (int o = 16; o > 0; o >>= 1) t += __shfl_down_sync(0xffffffffu, t, o);
        if (lane == 0) g_bsum[blockIdx.x] = t;
    }
}

// ---------------------------------------------------------------- scan stage 2
__global__ void k_scan2(int nb, int N) {
    if (threadIdx.x == 0 && blockIdx.x == 0) {
        int run = 0;
        for (int b = 0; b < nb; b++) { g_boff[b] = run; run += g_bsum[b]; }
        g_rowptr[N] = run;
    }
}

// ---------------------------------------------------------------- scan stage 3
__global__ void k_scan3(int N) {
    __shared__ int ws[32];
    int i = blockIdx.x * 1024 + threadIdx.x;
    int v = (i < N) ? g_cntall[i] : 0;
    int lane = threadIdx.x & 31, w = threadIdx.x >> 5;
    int x = v;
    #pragma unroll
    for (int o = 1; o < 32; o <<= 1) {
        int y = __shfl_up_sync(0xffffffffu, x, o);
        if (lane >= o) x += y;
    }
    if (lane == 31) ws[w] = x;
    __syncthreads();
    if (threadIdx.x < 32) {
        int t = ws[threadIdx.x];
        int y = t;
        #pragma unroll
        for (int o = 1; o < 32; o <<= 1) {
            int z = __shfl_up_sync(0xffffffffu, y, o);
            if (threadIdx.x >= o) y += z;
        }
        ws[threadIdx.x] = y - t;   // exclusive warp offset
    }
    __syncthreads();
    if (i < N) g_rowptr[i] = (x - v) + ws[w] + g_boff[blockIdx.x];
}

// ---------------------------------------------------------------- CSR scatter
__global__ void k_scatter(const int* __restrict__ ei,
                          const float* __restrict__ ew, int E, int N) {
    int e = blockIdx.x * blockDim.x + threadIdx.x;
    if (e >= E) return;
    float w = ew[e];
    if (w == 0.f) return;
    int s = clampi(ei[e], N);
    int d = clampi(ei[E + e], N);
    int pos = g_rowptr[d] + atomicAdd(&g_cursor[d], 1);
    float c;
    if (w > 0.f) c =  g_dinvp[s] * g_dinvp[d];
    else         c = -(g_dinvn[s] * g_dinvn[d]);
    g_esrc[pos]  = s;
    g_ecoef[pos] = c;
}

// ---------------------------------------------------------------- aggregation
// one warp per destination node; lane = 4 consecutive columns (4 halfs = 8B).
// Inner loop unrolled by 8 with round-to-8 padding: 8 independent gathers in
// flight (~11% padded work). Padded lanes carry c=0 -> contribute exactly 0.
__global__ void __launch_bounds__(256) k_agg(int insel, int N) {
    const __half* h = hbuf16(insel);
    int gw   = (blockIdx.x * blockDim.x + threadIdx.x) >> 5;
    int lane = threadIdx.x & 31;
    if (gw >= N) return;
    int v = gw;
    int beg = g_rowptr[v], end = g_rowptr[v + 1];

    float4 aP = make_float4(0.f, 0.f, 0.f, 0.f);
    float4 aN = make_float4(0.f, 0.f, 0.f, 0.f);

    for (int base = beg; base < end; base += 32) {
        int idx = base + lane;
        int s = 0; float c = 0.f;
        if (idx < end) { s = g_esrc[idx]; c = g_ecoef[idx]; }
        int cnt8 = (min(32, end - base) + 7) & ~7;
        for (int j = 0; j < cnt8; j += 8) {
            int   sj[8]; float cj[8]; uint2 raw[8];
            #pragma unroll
            for (int u = 0; u < 8; u++) {
                sj[u] = __shfl_sync(0xffffffffu, s, j + u);
                cj[u] = __shfl_sync(0xffffffffu, c, j + u);
            }
            #pragma unroll
            for (int u = 0; u < 8; u++)
                raw[u] = __ldg(((const uint2*)(h + (size_t)sj[u] * DD)) + lane);
            #pragma unroll
            for (int u = 0; u < 8; u++) {
                float2 f01 = __half22float2(*(__half2*)&raw[u].x);
                float2 f23 = __half22float2(*(__half2*)&raw[u].y);
                float cu = cj[u];
                if (cu > 0.f) {
                    aP.x += cu * f01.x; aP.y += cu * f01.y;
                    aP.z += cu * f23.x; aP.w += cu * f23.y;
                } else {
                    float m = -cu;               // cu==0 -> adds 0
                    aN.x += m * f01.x; aN.y += m * f01.y;
                    aN.z += m * f23.x; aN.w += m * f23.y;
                }
            }
        }
    }
    // self-loop terms
    uint2 raw = __ldg(((const uint2*)(h + (size_t)v * DD)) + lane);
    float2 f01 = __half22float2(*(__half2*)&raw.x);
    float2 f23 = __half22float2(*(__half2*)&raw.y);
    float sp = g_selfp[v], sn = g_selfn[v];
    aP.x += sp * f01.x; aP.y += sp * f01.y; aP.z += sp * f23.x; aP.w += sp * f23.y;
    aN.x += sn * f01.x; aN.y += sn * f01.y; aN.z += sn * f23.x; aN.w += sn * f23.y;

    uint2 zp, zn;
    *(__half2*)&zp.x = __floats2half2_rn(aP.x, aP.y);
    *(__half2*)&zp.y = __floats2half2_rn(aP.z, aP.w);
    *(__half2*)&zn.x = __floats2half2_rn(aN.x, aN.y);
    *(__half2*)&zn.y = __floats2half2_rn(aN.z, aN.w);
    ((uint2*)(g_zpos + (size_t)v * DD))[lane] = zp;
    ((uint2*)(g_zneg + (size_t)v * DD))[lane] = zn;
}

// ---------------------------------------------------------------- fp16 GEMM
// sub=0: out16 = fp16(relu(A@W + b));  sub=1: out16 = fp16(out16 - relu(A@W + b))
// A: [Mpad,128] fp16. W: precomputed fp16 hi/lo, n-major (k contiguous).
// m16n8k16 mma, fp32 acc. 256 thr = 8 warps; warp tile 32(m) x 64(n).
#define KC2   32
#define ASTR  40
__global__ void __launch_bounds__(256) k_gemm_f16(int asel, int widx,
                                                  const float* __restrict__ bias,
                                                  int outsel, int sub) {
    const __half* A = (asel == 0) ? g_zpos : g_zneg;
    const __half* Whi = g_whi + (size_t)widx * DD * DD;
    const __half* Wlo = g_wlo + (size_t)widx * DD * DD;
    __half* out = hbuf16(outsel);

    __shared__ __half As [128 * ASTR];
    __shared__ __half Bhi[128 * ASTR];
    __shared__ __half Blo[128 * ASTR];
    __shared__ float  bs [128];

    const int tid  = threadIdx.x;
    const int lane = tid & 31;
    const int wid  = tid >> 5;
    const int gr   = lane >> 2;
    const int ct   = lane & 3;
    const int wm   = (wid & 3) * 32;
    const int wn   = (wid >> 2) * 64;
    const int blockM = blockIdx.x * 128;

    if (tid < 128) bs[tid] = bias[tid];

    float acc[2][8][4];
    #pragma unroll
    for (int im = 0; im < 2; im++)
        #pragma unroll
        for (int in = 0; in < 8; in++)
            #pragma unroll
            for (int q = 0; q < 4; q++) acc[im][in][q] = 0.f;

    // B smem load indices: thread covers row n = tid>>1, 16 halfs at (tid&1)*16
    const int bn = tid >> 1;
    const int bk = (tid & 1) * 16;

    for (int k0 = 0; k0 < 128; k0 += KC2) {
        {
            int f = tid;
            #pragma unroll
            for (int it = 0; it < 2; it++, f += 256) {
                int row = f >> 2, kq = (f & 3) * 8;
                *(uint4*)&As[row * ASTR + kq] =
                    *(const uint4*)(A + (size_t)(blockM + row) * 128 + k0 + kq);
            }
        }
        {
            const __half* ph = Whi + (size_t)bn * DD + k0 + bk;
            const __half* pl = Wlo + (size_t)bn * DD + k0 + bk;
            *(uint4*)&Bhi[bn * ASTR + bk]     = *(const uint4*)ph;
            *(uint4*)&Bhi[bn * ASTR + bk + 8] = *(const uint4*)(ph + 8);
            *(uint4*)&Blo[bn * ASTR + bk]     = *(const uint4*)pl;
            *(uint4*)&Blo[bn * ASTR + bk + 8] = *(const uint4*)(pl + 8);
        }
        __syncthreads();

        #pragma unroll
        for (int ks = 0; ks < KC2; ks += 16) {
            uint32_t a[2][4];
            #pragma unroll
            for (int im = 0; im < 2; im++) {
                int r = wm + im * 16;
                a[im][0] = *(uint32_t*)&As[(r + gr)     * ASTR + ks + 2 * ct];
                a[im][1] = *(uint32_t*)&As[(r + 8 + gr) * ASTR + ks + 2 * ct];
                a[im][2] = *(uint32_t*)&As[(r + gr)     * ASTR + ks + 2 * ct + 8];
                a[im][3] = *(uint32_t*)&As[(r + 8 + gr) * ASTR + ks + 2 * ct + 8];
            }
            #pragma unroll
            for (int in = 0; in < 8; in++) {
                int n = wn + in * 8 + gr;
                uint32_t bh0 = *(uint32_t*)&Bhi[n * ASTR + ks + 2 * ct];
                uint32_t bh1 = *(uint32_t*)&Bhi[n * ASTR + ks + 2 * ct + 8];
                uint32_t bl0 = *(uint32_t*)&Blo[n * ASTR + ks + 2 * ct];
                uint32_t bl1 = *(uint32_t*)&Blo[n * ASTR + ks + 2 * ct + 8];
                #pragma unroll
                for (int im = 0; im < 2; im++) {
                    MMA_F16(acc[im][in][0], acc[im][in][1],
                            acc[im][in][2], acc[im][in][3],
                            a[im][0], a[im][1], a[im][2], a[im][3], bh0, bh1);
                    MMA_F16(acc[im][in][0], acc[im][in][1],
                            acc[im][in][2], acc[im][in][3],
                            a[im][0], a[im][1], a[im][2], a[im][3], bl0, bl1);
                }
            }
        }
        __syncthreads();
    }

    #pragma unroll
    for (int im = 0; im < 2; im++) {
        int r0 = blockM + wm + im * 16 + gr;
        #pragma unroll
        for (int in = 0; in < 8; in++) {
            int col = wn + in * 8 + ct * 2;
            float b0 = bs[col], b1 = bs[col + 1];
            __half2* p0 = (__half2*)(out + (size_t)r0 * 128 + col);
            __half2* p1 = (__half2*)(out + (size_t)(r0 + 8) * 128 + col);
            float r00 = fmaxf(acc[im][in][0] + b0, 0.f);
            float r01 = fmaxf(acc[im][in][1] + b1, 0.f);
            float r10 = fmaxf(acc[im][in][2] + b0, 0.f);
            float r11 = fmaxf(acc[im][in][3] + b1, 0.f);
            if (sub) {
                float2 o0 = __half22float2(*p0);
                float2 o1 = __half22float2(*p1);
                *p0 = __floats2half2_rn(o0.x - r00, o0.y - r01);
                *p1 = __floats2half2_rn(o1.x - r10, o1.y - r11);
            } else {
                *p0 = __floats2half2_rn(r00, r01);
                *p1 = __floats2half2_rn(r10, r11);
            }
        }
    }
}

// ---------------------------------------------------------------- mean pool
__global__ void k_pool(int insel, const int* __restrict__ batch, int N, int G) {
    const __half* h = hbuf16(insel);
    int t = threadIdx.x;
    int v0 = blockIdx.x * 128;
    int vend = min(v0 + 128, N);
    float acc = 0.f;
    int curg = -1, cnt = 0;
    for (int v = v0; v < vend; v++) {
        int g = clampi(batch[v], G);
        if (g != curg) {
            if (curg >= 0) {
                atomicAdd(&g_pool[curg * DD + t], acc);
                if (t == 0) atomicAdd(&g_pcnt[curg], cnt);
            }
            curg = g; acc = 0.f; cnt = 0;
        }
        acc += __half2float(h[(size_t)v * DD + t]);
        cnt++;
    }
    if (curg >= 0) {
        atomicAdd(&g_pool[curg * DD + t], acc);
        if (t == 0) atomicAdd(&g_pcnt[curg], cnt);
    }
}

// ---------------------------------------------------------------- layernorm
__global__ void k_ln(const float* __restrict__ gamma,
                     const float* __restrict__ beta,
                     float* __restrict__ out) {
    __shared__ float sm[4];
    int g = blockIdx.x, t = threadIdx.x;
    int lane = t & 31, w = t >> 5;
    float cnt = fmaxf((float)g_pcnt[g], 1.f);
    float v = g_pool[g * DD + t] / cnt;

    float s = v;
    #pragma unroll
    for (int o = 16; o > 0; o >>= 1) s += __shfl_xor_sync(0xffffffffu, s, o);
    if (lane == 0) sm[w] = s;
    __syncthreads();
    float mu = (sm[0] + sm[1] + sm[2] + sm[3]) * (1.f / 128.f);
    __syncthreads();

    float d = v - mu;
    float s2 = d * d;
    #pragma unroll
    for (int o = 16; o > 0; o >>= 1) s2 += __shfl_xor_sync(0xffffffffu, s2, o);
    if (lane == 0) sm[w] = s2;
    __syncthreads();
    float var = (sm[0] + sm[1] + sm[2] + sm[3]) * (1.f / 128.f);

    out[g * DD + t] = d * rsqrtf(var + EPSLN) * gamma[t] + beta[t];
}

// ---------------------------------------------------------------- launch
extern "C" void kernel_launch(void* const* d_in, const int* in_sizes, int n_in,
                              void* d_out, int out_size) {
    const float* x     = (const float*)d_in[0];
    const int*   ei    = (const int*)d_in[1];
    const float* ew    = (const float*)d_in[2];
    const int*   batch = (const int*)d_in[3];
    const float* Wp    = (const float*)d_in[4];
    const float* bp    = (const float*)d_in[5];
    const float* Wn    = (const float*)d_in[6];
    const float* bn    = (const float*)d_in[7];
    const float* gamma = (const float*)d_in[8];
    const float* beta  = (const float*)d_in[9];

    int N = in_sizes[0] / DD;
    int E = in_sizes[1] / 2;
    int L = in_sizes[4] / (DD * DD);
    int G = out_size / DD;

    int nbN  = (N + 255) / 256;
    int nbE  = (E + 255) / 256;
    int nbSc = (N + 1023) / 1024;
    int nbAg = (N * 32 + 255) / 256;          // one warp per node
    int nbGm = (N + 127) / 128;               // 128-row GEMM tiles
    int nbPl = (N + 127) / 128;
    int nbCv = (N * DD / 2 + 255) / 256;      // x->fp16 (2 elems/thread)
    int nbWp = (L * 2 * DD * DD + 255) / 256; // W precompute

    // preprocessing (per call; deterministic structure)
    k_init<<<nbN, 256>>>(N);
    k_x2h<<<nbCv, 256>>>(x, N * DD / 2);
    k_wprep<<<nbWp, 256>>>(Wp, Wn, L);
    k_degree<<<nbE, 256>>>(ei, ew, E, N);
    k_nodeparams<<<nbN, 256>>>(N);
    k_scan1<<<nbSc, 1024>>>(N);
    k_scan2<<<1, 32>>>(nbSc, N);
    k_scan3<<<nbSc, 1024>>>(N);
    k_scatter<<<nbE, 256>>>(ei, ew, E, N);

    // layers: h16A holds x (layer0 input); ping-pong A(0)/B(1)
    int insel = 0;
    for (int l = 0; l < L; l++) {
        k_agg<<<nbAg, 256>>>(insel, N);
        int outsel = insel ^ 1;
        k_gemm_f16<<<nbGm, 256>>>(0, l * 2,     bp + (size_t)l * DD, outsel, 0);
        k_gemm_f16<<<nbGm, 256>>>(1, l * 2 + 1, bn + (size_t)l * DD, outsel, 1);
        insel = outsel;
    }

    // pool + layernorm
    k_pool<<<nbPl, 128>>>(insel, batch, N, G);
    k_ln<<<G, 128>>>(gamma, beta, (float*)d_out);
}

// round 17
// speedup vs baseline: 1.5449x; 1.0083x over previous
#include <cuda_runtime.h>
#include <cuda_fp16.h>
#include <cstdint>

// ---------------------------------------------------------------------------
// Signed 3-layer GCN + mean-pool + LayerNorm.
//   per layer: z_pos/z_neg = (A_sign + selfdiag) @ h   (one edge pass, CSR by dst)
//              h' = relu(z_pos@Wp + bp) - relu(z_neg@Wn + bn)   (ONE fused GEMM)
// h AND z live in fp16. GEMM: fp16 m16n8k16 mma, W pre-split fp16 hi+lo once
// per call (k_wprep, n-major), fp32 accumulate, dual accumulators (pos+neg),
// single h' write. edge_index / batch are int32.
// ---------------------------------------------------------------------------

#define DD    128
#define MAXN  100352            // 784 * 128, padded node capacity
#define MAXE  3200000
#define MAXG  64
#define MAXL  3
#define EPSLN 1e-5f

__device__ __half g_zpos[(size_t)MAXN * DD];
__device__ __half g_zneg[(size_t)MAXN * DD];
__device__ __half g_h16A[(size_t)MAXN * DD];
__device__ __half g_h16B[(size_t)MAXN * DD];
__device__ __half g_whi[(size_t)MAXL * 2 * DD * DD];   // [mat][n][k] n-major
__device__ __half g_wlo[(size_t)MAXL * 2 * DD * DD];
__device__ int    g_esrc [MAXE];
__device__ float  g_ecoef[MAXE];
__device__ int    g_rowptr[MAXN + 1];
__device__ int    g_cntp[MAXN];
__device__ int    g_cntn[MAXN];
__device__ int    g_cursor[MAXN];
__device__ int    g_cntall[MAXN];
__device__ float  g_dinvp[MAXN];
__device__ float  g_dinvn[MAXN];
__device__ float  g_selfp[MAXN];
__device__ float  g_selfn[MAXN];
__device__ int    g_bsum[256];
__device__ int    g_boff[256];
__device__ float  g_pool[MAXG * DD];
__device__ int    g_pcnt[MAXG];

__device__ __forceinline__ __half* hbuf16(int s) { return s == 0 ? g_h16A : g_h16B; }
__device__ __forceinline__ int clampi(int v, int hi) {
    return v < 0 ? 0 : (v >= hi ? hi - 1 : v);
}

#define MMA_F16(d0,d1,d2,d3,a0,a1,a2,a3,b0,b1)                               \
    asm volatile("mma.sync.aligned.m16n8k16.row.col.f32.f16.f16.f32 "        \
                 "{%0,%1,%2,%3}, {%4,%5,%6,%7}, {%8,%9}, {%0,%1,%2,%3};"     \
                 : "+f"(d0), "+f"(d1), "+f"(d2), "+f"(d3)                    \
                 : "r"(a0), "r"(a1), "r"(a2), "r"(a3), "r"(b0), "r"(b1))

// ---------------------------------------------------------------- init + x->fp16
__global__ void k_init_x2h(const float* __restrict__ x, int N, int totalh) {
    int i = blockIdx.x * blockDim.x + threadIdx.x;
    if (i < N) { g_cntp[i] = 0; g_cntn[i] = 0; g_cursor[i] = 0; }
    if (i < MAXG * DD) g_pool[i] = 0.f;
    if (i < MAXG) g_pcnt[i] = 0;
    if (i < totalh) {
        float2 v = *(const float2*)(x + (size_t)i * 2);
        *(__half2*)(g_h16A + (size_t)i * 2) = __floats2half2_rn(v.x, v.y);
    }
}

// ---------------------------------------------------------------- W -> fp16 hi/lo
// Wp/Wn are [L][k][n] row-major fp32. Output n-major: g_whi[mat][n*128+k],
// mat = l*2 (pos) / l*2+1 (neg).
__global__ void k_wprep(const float* __restrict__ Wp,
                        const float* __restrict__ Wn, int L) {
    int i = blockIdx.x * blockDim.x + threadIdx.x;
    int total = L * 2 * DD * DD;
    if (i >= total) return;
    int k   = i & 127;
    int n   = (i >> 7) & 127;
    int mat = i >> 14;           // 0..2L-1
    int l   = mat >> 1;
    const float* W = (mat & 1) ? Wn : Wp;
    float w = W[(size_t)l * DD * DD + k * DD + n];
    __half hi = __float2half_rn(w);
    float lo = w - __half2float(hi);
    g_whi[(size_t)mat * DD * DD + n * DD + k] = hi;
    g_wlo[(size_t)mat * DD * DD + n * DD + k] = __float2half_rn(lo);
}

// ---------------------------------------------------------------- degree count
__global__ void k_degree(const int* __restrict__ ei,
                         const float* __restrict__ ew, int E, int N) {
    int e = blockIdx.x * blockDim.x + threadIdx.x;
    if (e >= E) return;
    int dst = clampi(ei[E + e], N);
    float w = ew[e];
    if (w > 0.f)      atomicAdd(&g_cntp[dst], 1);
    else if (w < 0.f) atomicAdd(&g_cntn[dst], 1);
}

// ---------------------------------------------------------------- node params
__global__ void k_nodeparams(int N) {
    int v = blockIdx.x * blockDim.x + threadIdx.x;
    if (v >= N) return;
    int cp = g_cntp[v], cn = g_cntn[v];
    float dp = 1.f + (float)cp;
    float dn = 1.f + (float)cn;
    g_dinvp[v] = rsqrtf(dp);
    g_dinvn[v] = rsqrtf(dn);
    g_selfp[v] = 1.f / dp;
    g_selfn[v] = 1.f / dn;
    g_cntall[v] = cp + cn;
}

// ---------------------------------------------------------------- scan stage 1
__global__ void k_scan1(int N) {
    __shared__ int sm[32];
    int i = blockIdx.x * 1024 + threadIdx.x;
    int v = (i < N) ? g_cntall[i] : 0;
    int lane = threadIdx.x & 31, w = threadIdx.x >> 5;
    #pragma unroll
    for (int o = 16; o > 0; o >>= 1) v += __shfl_down_sync(0xffffffffu, v, o);
    if (lane == 0) sm[w] = v;
    __syncthreads();
    if (w == 0) {
        int t = sm[lane];
        #pragma unroll
        for (int o = 16; o > 0; o >>= 1) t += __shfl_down_sync(0xffffffffu, t, o);
        if (lane == 0) g_bsum[blockIdx.x] = t;
    }
}

// ---------------------------------------------------------------- scan stage 2
__global__ void k_scan2(int nb, int N) {
    if (threadIdx.x == 0 && blockIdx.x == 0) {
        int run = 0;
        for (int b = 0; b < nb; b++) { g_boff[b] = run; run += g_bsum[b]; }
        g_rowptr[N] = run;
    }
}

// ---------------------------------------------------------------- scan stage 3
__global__ void k_scan3(int N) {
    __shared__ int ws[32];
    int i = blockIdx.x * 1024 + threadIdx.x;
    int v = (i < N) ? g_cntall[i] : 0;
    int lane = threadIdx.x & 31, w = threadIdx.x >> 5;
    int x = v;
    #pragma unroll
    for (int o = 1; o < 32; o <<= 1) {
        int y = __shfl_up_sync(0xffffffffu, x, o);
        if (lane >= o) x += y;
    }
    if (lane == 31) ws[w] = x;
    __syncthreads();
    if (threadIdx.x < 32) {
        int t = ws[threadIdx.x];
        int y = t;
        #pragma unroll
        for (int o = 1; o < 32; o <<= 1) {
            int z = __shfl_up_sync(0xffffffffu, y, o);
            if (threadIdx.x >= o) y += z;
        }
        ws[threadIdx.x] = y - t;   // exclusive warp offset
    }
    __syncthreads();
    if (i < N) g_rowptr[i] = (x - v) + ws[w] + g_boff[blockIdx.x];
}

// ---------------------------------------------------------------- CSR scatter
__global__ void k_scatter(const int* __restrict__ ei,
                          const float* __restrict__ ew, int E, int N) {
    int e = blockIdx.x * blockDim.x + threadIdx.x;
    if (e >= E) return;
    float w = ew[e];
    if (w == 0.f) return;
    int s = clampi(ei[e], N);
    int d = clampi(ei[E + e], N);
    int pos = g_rowptr[d] + atomicAdd(&g_cursor[d], 1);
    float c;
    if (w > 0.f) c =  g_dinvp[s] * g_dinvp[d];
    else         c = -(g_dinvn[s] * g_dinvn[d]);
    g_esrc[pos]  = s;
    g_ecoef[pos] = c;
}

// ---------------------------------------------------------------- aggregation
// one warp per destination node; lane = 4 consecutive columns (4 halfs = 8B).
// Inner loop unrolled by 8 with round-to-8 padding: 8 independent gathers in
// flight (~11% padded work). Padded lanes carry c=0 -> contribute exactly 0.
__global__ void __launch_bounds__(256) k_agg(int insel, int N) {
    const __half* h = hbuf16(insel);
    int gw   = (blockIdx.x * blockDim.x + threadIdx.x) >> 5;
    int lane = threadIdx.x & 31;
    if (gw >= N) return;
    int v = gw;
    int beg = g_rowptr[v], end = g_rowptr[v + 1];

    float4 aP = make_float4(0.f, 0.f, 0.f, 0.f);
    float4 aN = make_float4(0.f, 0.f, 0.f, 0.f);

    for (int base = beg; base < end; base += 32) {
        int idx = base + lane;
        int s = 0; float c = 0.f;
        if (idx < end) { s = g_esrc[idx]; c = g_ecoef[idx]; }
        int cnt8 = (min(32, end - base) + 7) & ~7;
        for (int j = 0; j < cnt8; j += 8) {
            int   sj[8]; float cj[8]; uint2 raw[8];
            #pragma unroll
            for (int u = 0; u < 8; u++) {
                sj[u] = __shfl_sync(0xffffffffu, s, j + u);
                cj[u] = __shfl_sync(0xffffffffu, c, j + u);
            }
            #pragma unroll
            for (int u = 0; u < 8; u++)
                raw[u] = __ldg(((const uint2*)(h + (size_t)sj[u] * DD)) + lane);
            #pragma unroll
            for (int u = 0; u < 8; u++) {
                float2 f01 = __half22float2(*(__half2*)&raw[u].x);
                float2 f23 = __half22float2(*(__half2*)&raw[u].y);
                float cu = cj[u];
                if (cu > 0.f) {
                    aP.x += cu * f01.x; aP.y += cu * f01.y;
                    aP.z += cu * f23.x; aP.w += cu * f23.y;
                } else {
                    float m = -cu;               // cu==0 -> adds 0
                    aN.x += m * f01.x; aN.y += m * f01.y;
                    aN.z += m * f23.x; aN.w += m * f23.y;
                }
            }
        }
    }
    // self-loop terms
    uint2 raw = __ldg(((const uint2*)(h + (size_t)v * DD)) + lane);
    float2 f01 = __half22float2(*(__half2*)&raw.x);
    float2 f23 = __half22float2(*(__half2*)&raw.y);
    float sp = g_selfp[v], sn = g_selfn[v];
    aP.x += sp * f01.x; aP.y += sp * f01.y; aP.z += sp * f23.x; aP.w += sp * f23.y;
    aN.x += sn * f01.x; aN.y += sn * f01.y; aN.z += sn * f23.x; aN.w += sn * f23.y;

    uint2 zp, zn;
    *(__half2*)&zp.x = __floats2half2_rn(aP.x, aP.y);
    *(__half2*)&zp.y = __floats2half2_rn(aP.z, aP.w);
    *(__half2*)&zn.x = __floats2half2_rn(aN.x, aN.y);
    *(__half2*)&zn.y = __floats2half2_rn(aN.z, aN.w);
    ((uint2*)(g_zpos + (size_t)v * DD))[lane] = zp;
    ((uint2*)(g_zneg + (size_t)v * DD))[lane] = zn;
}

// ---------------------------------------------------------------- fused GEMM
// h' = fp16(relu(zpos@Wp + bp) - relu(zneg@Wn + bn)); single write.
// W precomputed fp16 hi/lo, n-major. m16n8k16 mma, fp32 acc.
// 256 thr = 8 warps; warp tile 32(m) x 64(n); dual accumulator sets.
#define KC2   32
#define ASTR  40
__global__ void __launch_bounds__(256, 1) k_gemm_dual(int lidx,
                                                      const float* __restrict__ bp,
                                                      const float* __restrict__ bn,
                                                      int outsel) {
    const __half* WhiP = g_whi + (size_t)(lidx * 2)     * DD * DD;
    const __half* WloP = g_wlo + (size_t)(lidx * 2)     * DD * DD;
    const __half* WhiN = g_whi + (size_t)(lidx * 2 + 1) * DD * DD;
    const __half* WloN = g_wlo + (size_t)(lidx * 2 + 1) * DD * DD;
    __half* out = hbuf16(outsel);

    __shared__ __half As [128 * ASTR];
    __shared__ __half Bhi[128 * ASTR];
    __shared__ __half Blo[128 * ASTR];
    __shared__ float  bsp[128];
    __shared__ float  bsn[128];

    const int tid  = threadIdx.x;
    const int lane = tid & 31;
    const int wid  = tid >> 5;
    const int gr   = lane >> 2;
    const int ct   = lane & 3;
    const int wm   = (wid & 3) * 32;
    const int wn   = (wid >> 2) * 64;
    const int blockM = blockIdx.x * 128;

    if (tid < 128) { bsp[tid] = bp[tid]; bsn[tid] = bn[tid]; }

    float accP[2][8][4];
    float accN[2][8][4];
    #pragma unroll
    for (int im = 0; im < 2; im++)
        #pragma unroll
        for (int in = 0; in < 8; in++)
            #pragma unroll
            for (int q = 0; q < 4; q++) { accP[im][in][q] = 0.f; accN[im][in][q] = 0.f; }

    const int bn_row = tid >> 1;
    const int bk     = (tid & 1) * 16;

    #pragma unroll
    for (int phase = 0; phase < 2; phase++) {
        const __half* A   = phase ? g_zneg : g_zpos;
        const __half* Whi = phase ? WhiN : WhiP;
        const __half* Wlo = phase ? WloN : WloP;

        for (int k0 = 0; k0 < 128; k0 += KC2) {
            {
                int f = tid;
                #pragma unroll
                for (int it = 0; it < 2; it++, f += 256) {
                    int row = f >> 2, kq = (f & 3) * 8;
                    *(uint4*)&As[row * ASTR + kq] =
                        *(const uint4*)(A + (size_t)(blockM + row) * 128 + k0 + kq);
                }
            }
            {
                const __half* ph = Whi + (size_t)bn_row * DD + k0 + bk;
                const __half* pl = Wlo + (size_t)bn_row * DD + k0 + bk;
                *(uint4*)&Bhi[bn_row * ASTR + bk]     = *(const uint4*)ph;
                *(uint4*)&Bhi[bn_row * ASTR + bk + 8] = *(const uint4*)(ph + 8);
                *(uint4*)&Blo[bn_row * ASTR + bk]     = *(const uint4*)pl;
                *(uint4*)&Blo[bn_row * ASTR + bk + 8] = *(const uint4*)(pl + 8);
            }
            __syncthreads();

            #pragma unroll
            for (int ks = 0; ks < KC2; ks += 16) {
                uint32_t a[2][4];
                #pragma unroll
                for (int im = 0; im < 2; im++) {
                    int r = wm + im * 16;
                    a[im][0] = *(uint32_t*)&As[(r + gr)     * ASTR + ks + 2 * ct];
                    a[im][1] = *(uint32_t*)&As[(r + 8 + gr) * ASTR + ks + 2 * ct];
                    a[im][2] = *(uint32_t*)&As[(r + gr)     * ASTR + ks + 2 * ct + 8];
                    a[im][3] = *(uint32_t*)&As[(r + 8 + gr) * ASTR + ks + 2 * ct + 8];
                }
                #pragma unroll
                for (int in = 0; in < 8; in++) {
                    int n = wn + in * 8 + gr;
                    uint32_t bh0 = *(uint32_t*)&Bhi[n * ASTR + ks + 2 * ct];
                    uint32_t bh1 = *(uint32_t*)&Bhi[n * ASTR + ks + 2 * ct + 8];
                    uint32_t bl0 = *(uint32_t*)&Blo[n * ASTR + ks + 2 * ct];
                    uint32_t bl1 = *(uint32_t*)&Blo[n * ASTR + ks + 2 * ct + 8];
                    #pragma unroll
                    for (int im = 0; im < 2; im++) {
                        float* ac = phase ? accN[im][in] : accP[im][in];
                        MMA_F16(ac[0], ac[1], ac[2], ac[3],
                                a[im][0], a[im][1], a[im][2], a[im][3], bh0, bh1);
                        MMA_F16(ac[0], ac[1], ac[2], ac[3],
                                a[im][0], a[im][1], a[im][2], a[im][3], bl0, bl1);
                    }
                }
            }
            __syncthreads();
        }
    }

    // epilogue: h' = relu(accP + bp) - relu(accN + bn), fp16, single write
    #pragma unroll
    for (int im = 0; im < 2; im++) {
        int r0 = blockM + wm + im * 16 + gr;
        #pragma unroll
        for (int in = 0; in < 8; in++) {
            int col = wn + in * 8 + ct * 2;
            float bp0 = bsp[col], bp1 = bsp[col + 1];
            float bn0 = bsn[col], bn1 = bsn[col + 1];
            float v00 = fmaxf(accP[im][in][0] + bp0, 0.f) - fmaxf(accN[im][in][0] + bn0, 0.f);
            float v01 = fmaxf(accP[im][in][1] + bp1, 0.f) - fmaxf(accN[im][in][1] + bn1, 0.f);
            float v10 = fmaxf(accP[im][in][2] + bp0, 0.f) - fmaxf(accN[im][in][2] + bn0, 0.f);
            float v11 = fmaxf(accP[im][in][3] + bp1, 0.f) - fmaxf(accN[im][in][3] + bn1, 0.f);
            *(__half2*)(out + (size_t)r0 * 128 + col)       = __floats2half2_rn(v00, v01);
            *(__half2*)(out + (size_t)(r0 + 8) * 128 + col) = __floats2half2_rn(v10, v11);
        }
    }
}

// ---------------------------------------------------------------- mean pool
__global__ void k_pool(int insel, const int* __restrict__ batch, int N, int G) {
    const __half* h = hbuf16(insel);
    int t = threadIdx.x;
    int v0 = blockIdx.x * 128;
    int vend = min(v0 + 128, N);
    float acc = 0.f;
    int curg = -1, cnt = 0;
    for (int v = v0; v < vend; v++) {
        int g = clampi(batch[v], G);
        if (g != curg) {
            if (curg >= 0) {
                atomicAdd(&g_pool[curg * DD + t], acc);
                if (t == 0) atomicAdd(&g_pcnt[curg], cnt);
            }
            curg = g; acc = 0.f; cnt = 0;
        }
        acc += __half2float(h[(size_t)v * DD + t]);
        cnt++;
    }
    if (curg >= 0) {
        atomicAdd(&g_pool[curg * DD + t], acc);
        if (t == 0) atomicAdd(&g_pcnt[curg], cnt);
    }
}

// ---------------------------------------------------------------- layernorm
__global__ void k_ln(const float* __restrict__ gamma,
                     const float* __restrict__ beta,
                     float* __restrict__ out) {
    __shared__ float sm[4];
    int g = blockIdx.x, t = threadIdx.x;
    int lane = t & 31, w = t >> 5;
    float cnt = fmaxf((float)g_pcnt[g], 1.f);
    float v = g_pool[g * DD + t] / cnt;

    float s = v;
    #pragma unroll
    for (int o = 16; o > 0; o >>= 1) s += __shfl_xor_sync(0xffffffffu, s, o);
    if (lane == 0) sm[w] = s;
    __syncthreads();
    float mu = (sm[0] + sm[1] + sm[2] + sm[3]) * (1.f / 128.f);
    __syncthreads();

    float d = v - mu;
    float s2 = d * d;
    #pragma unroll
    for (int o = 16; o > 0; o >>= 1) s2 += __shfl_xor_sync(0xffffffffu, s2, o);
    if (lane == 0) sm[w] = s2;
    __syncthreads();
    float var = (sm[0] + sm[1] + sm[2] + sm[3]) * (1.f / 128.f);

    out[g * DD + t] = d * rsqrtf(var + EPSLN) * gamma[t] + beta[t];
}

// ---------------------------------------------------------------- launch
extern "C" void kernel_launch(void* const* d_in, const int* in_sizes, int n_in,
                              void* d_out, int out_size) {
    const float* x     = (const float*)d_in[0];
    const int*   ei    = (const int*)d_in[1];
    const float* ew    = (const float*)d_in[2];
    const int*   batch = (const int*)d_in[3];
    const float* Wp    = (const float*)d_in[4];
    const float* bp    = (const float*)d_in[5];
    const float* Wn    = (const float*)d_in[6];
    const float* bn    = (const float*)d_in[7];
    const float* gamma = (const float*)d_in[8];
    const float* beta  = (const float*)d_in[9];

    int N = in_sizes[0] / DD;
    int E = in_sizes[1] / 2;
    int L = in_sizes[4] / (DD * DD);
    int G = out_size / DD;

    int nbE  = (E + 255) / 256;
    int nbN  = (N + 255) / 256;
    int nbSc = (N + 1023) / 1024;
    int nbAg = (N * 32 + 255) / 256;          // one warp per node
    int nbGm = (N + 127) / 128;               // 128-row GEMM tiles
    int nbPl = (N + 127) / 128;
    int nbIx = (N * DD / 2 + 255) / 256;      // init + x->fp16
    int nbWp = (L * 2 * DD * DD + 255) / 256; // W precompute

    // preprocessing (per call; deterministic structure)
    k_init_x2h<<<nbIx, 256>>>(x, N, N * DD / 2);
    k_wprep<<<nbWp, 256>>>(Wp, Wn, L);
    k_degree<<<nbE, 256>>>(ei, ew, E, N);
    k_nodeparams<<<nbN, 256>>>(N);
    k_scan1<<<nbSc, 1024>>>(N);
    k_scan2<<<1, 32>>>(nbSc, N);
    k_scan3<<<nbSc, 1024>>>(N);
    k_scatter<<<nbE, 256>>>(ei, ew, E, N);

    // layers: h16A holds x (layer0 input); ping-pong A(0)/B(1)
    int insel = 0;
    for (int l = 0; l < L; l++) {
        k_agg<<<nbAg, 256>>>(insel, N);
        int outsel = insel ^ 1;
        k_gemm_dual<<<nbGm, 256>>>(l, bp + (size_t)l * DD, bn + (size_t)l * DD, outsel);
        insel = outsel;
    }

    // pool + layernorm
    k_pool<<<nbPl, 128>>>(insel, batch, N, G);
    k_ln<<<G, 128>>>(gamma, beta, (float*)d_out);
}